// round 8
// baseline (speedup 1.0000x reference)
#include <cuda_runtime.h>
#include <cuda_fp16.h>
#include <cstdint>

#define NT 2560
#define DD 32
#define NB 4
#define BN 32
#define BM 128
#define MSPLIT 2
#define NITH 10                       // m-tiles per block (20 / MSPLIT)
#define NTHREADS 256

// ---- partial-kernel smem ----
#define SM_XNH 0
#define SM_BUF 2560
#define OFF_XMH 0
#define OFF_HTH 10240
#define BUFSZ   18944                 // per stage (XM + HT)
#define SMEM_P  (SM_BUF + 3 * BUFSZ)  // 59392, 3-stage ring
#define SM_AGG  SM_BUF

// ---- device globals (allocation-free scratch) ----
__device__ float    g_h1 [NB * NT * DD];
__device__ float    g_agg[MSPLIT * NB * NT * DD];
__device__ uint32_t g_xhi [NB * NT * DD / 2];   // X fp16x2 [b][row][16]
__device__ uint32_t g_hthi[NB * DD * NT / 2];   // H^T fp16x2 [b][d][1280]

__device__ __forceinline__ uint32_t smem_u32(const void* p) {
  uint32_t a;
  asm("{ .reg .u64 t; cvta.to.shared.u64 t, %1; cvt.u32.u64 %0, t; }" : "=r"(a) : "l"(p));
  return a;
}
__device__ __forceinline__ void mma16816(float c[4], const uint32_t a[4],
                                         const uint32_t b[2]) {
  asm volatile(
      "mma.sync.aligned.m16n8k16.row.col.f32.f16.f16.f32 "
      "{%0,%1,%2,%3}, {%4,%5,%6,%7}, {%8,%9}, {%0,%1,%2,%3};"
      : "+f"(c[0]), "+f"(c[1]), "+f"(c[2]), "+f"(c[3])
      : "r"(a[0]), "r"(a[1]), "r"(a[2]), "r"(a[3]), "r"(b[0]), "r"(b[1]));
}
__device__ __forceinline__ void ldsm4(uint32_t r[4], uint32_t addr) {
  asm volatile("ldmatrix.sync.aligned.m8n8.x4.shared.b16 {%0,%1,%2,%3}, [%4];"
               : "=r"(r[0]), "=r"(r[1]), "=r"(r[2]), "=r"(r[3]) : "r"(addr));
}
__device__ __forceinline__ void cp16(uint32_t dst, const void* src) {
  asm volatile("cp.async.cg.shared.global [%0], [%1], 16;" :: "r"(dst), "l"(src));
}
#define CP_COMMIT() asm volatile("cp.async.commit_group;")
template <int N> __device__ __forceinline__ void cp_wait() {
  asm volatile("cp.async.wait_group %0;" :: "n"(N));
}
__device__ __forceinline__ float tanh_relu(float s) {
  float r = fmaxf(s, 0.0f), v;
  asm("tanh.approx.f32 %0, %1;" : "=f"(v) : "f"(r));
  return v;
}
__device__ __forceinline__ uint32_t pack_h2(float x, float y) {
  __half2 h = __floats2half2_rn(x, y);
  return *reinterpret_cast<uint32_t*>(&h);
}

// ---- prep: fp16-convert X rows + write transposed fp16 (layer 1 only) ----
__global__ void prep_kernel(const float* __restrict__ src) {
  __shared__ uint32_t sxh[64][20];
  const int t = threadIdx.x, b = blockIdx.y, r0 = blockIdx.x * 64;
  {
    const int row = t >> 2, q = t & 3;
    const float4* p = (const float4*)(src + ((size_t)b * NT + r0 + row) * DD + q * 8);
    float4 v0 = p[0], v1 = p[1];
    uint4 hv = make_uint4(pack_h2(v0.x, v0.y), pack_h2(v0.z, v0.w),
                          pack_h2(v1.x, v1.y), pack_h2(v1.z, v1.w));
    *(uint4*)&sxh[row][q * 4] = hv;
    size_t xi = ((size_t)b * NT + r0 + row) * 16 + q * 4;
    *(uint4*)&g_xhi[xi] = hv;
  }
  __syncthreads();
  {
    const int d = t >> 3;
    const uint32_t sh = (d & 1) * 16;
    const size_t obase = ((size_t)b * DD + d) * (NT / 2) + (r0 >> 1);
    #pragma unroll
    for (int j = 0; j < 4; ++j) {
      const int p = (t & 7) * 4 + j;
      uint32_t h0 = (sxh[2 * p][d >> 1] >> sh) & 0xffffu;
      uint32_t h1 = (sxh[2 * p + 1][d >> 1] >> sh) & 0xffffu;
      g_hthi[obase + p] = h0 | (h1 << 16);
    }
  }
}

// ---- partial: agg_mz = sum over this block's 10 m-tiles of tanh(relu(S))·H ----
__global__ __launch_bounds__(NTHREADS, 3)
void gnn_partial()
{
  extern __shared__ char sm[];
  const uint32_t sb = smem_u32(sm);
  const int t = threadIdx.x, lane = t & 31, wid = t >> 5;
  const int wr = wid >> 2, wc = wid & 3, g = lane >> 2, tig = lane & 3;
  const int bx = blockIdx.x, b = blockIdx.y, mz = blockIdx.z;
  const int n0 = bx * BN;
  const int mtdiag = bx >> 2, doff = (bx & 3) * 32;

  // Xn tile (persistent): 32 rows x 64B fp16
  {
    const int row = t >> 3, q = t & 7;
    const size_t xi = ((size_t)b * NT + n0 + row) * 16 + q * 2;
    *(uint2*)(sm + SM_XNH + row * 80 + q * 8) = *(const uint2*)(g_xhi + xi);
  }

  // tile-issue via cp.async (4x16B per thread); stage = local index % 3
  auto issue = [&](int i) {
    const int m0 = (mz * NITH + i) * BM;
    const uint32_t base = sb + SM_BUF + (uint32_t)(i % 3) * BUFSZ;
    const size_t xbase = ((size_t)b * NT + m0) * 16;
    const size_t hbase = (size_t)b * DD * (NT / 2) + (m0 >> 1);
    #pragma unroll
    for (int k = 0; k < 2; ++k) {
      const int c = t + k * 256;
      const int row = c >> 2, q = c & 3;
      cp16(base + OFF_XMH + row * 80 + q * 16, g_xhi + xbase + row * 16 + q * 4);
      const int d = c >> 4, q2 = c & 15;
      cp16(base + OFF_HTH + d * 272 + q2 * 16, g_hthi + hbase + (size_t)d * (NT / 2) + q2 * 4);
    }
    CP_COMMIT();
  };

  // ---- ldmatrix lane addresses ----
  const uint32_t a_addr = sb + SM_XNH +
      (uint32_t)(16 * wr + 8 * ((lane >> 3) & 1) + (lane & 7)) * 80u +
      (uint32_t)(lane >> 4) * 16u;
  const uint32_t b1_addr = OFF_XMH +
      (uint32_t)(32 * wc + 8 * (lane >> 4) + (lane & 7)) * 80u +
      (uint32_t)((lane >> 3) & 1) * 16u;
  const uint32_t b2_addr = OFF_HTH +
      (uint32_t)(8 * (lane >> 4) + (lane & 7)) * 272u +
      (uint32_t)(64 * wc) + (uint32_t)((lane >> 3) & 1) * 16u;

  float acc2[4][4];
  #pragma unroll
  for (int nc = 0; nc < 4; ++nc)
    #pragma unroll
    for (int e = 0; e < 4; ++e) acc2[nc][e] = 0.0f;

  issue(0);
  __syncthreads();                       // Xn stores visible

  uint32_t AH[2][4];                     // loop-invariant A (Xn)
  ldsm4(AH[0], a_addr);
  ldsm4(AH[1], a_addr + 32);

  for (int i = 0; i < NITH; ++i) {
    if (i + 1 < NITH) { issue(i + 1); cp_wait<1>(); }
    else              { cp_wait<0>(); }
    __syncthreads();   // single barrier/iter: stage (i+1)%3 was last read 2 iters ago

    const uint32_t buf = sb + SM_BUF + (uint32_t)(i % 3) * BUFSZ;
    const int mt = mz * NITH + i;
    const bool diag = (mt == mtdiag);

    // ---- all B fragments up front ----
    uint32_t BH[2][2][4], BH2[2][2][4];
    #pragma unroll
    for (int kt = 0; kt < 2; ++kt)
      #pragma unroll
      for (int p = 0; p < 2; ++p) {
        ldsm4(BH[kt][p],  buf + b1_addr + p * 1280u + kt * 32u);
        ldsm4(BH2[kt][p], buf + b2_addr + p * 4352u + kt * 32u);
      }

    // ---- phase 1: S = Xn·Xm^T ----
    float acc[4][4];
    #pragma unroll
    for (int mc = 0; mc < 4; ++mc)
      #pragma unroll
      for (int e = 0; e < 4; ++e) acc[mc][e] = 0.0f;
    #pragma unroll
    for (int kt = 0; kt < 2; ++kt)
      #pragma unroll
      for (int mc = 0; mc < 4; ++mc)
        mma16816(acc[mc], AH[kt], &BH[kt][mc >> 1][(mc & 1) * 2]);

    // ---- nonlinearity + self-loop -> phase-2 A frags ----
    uint32_t sA2[8];
    #pragma unroll
    for (int mc = 0; mc < 4; ++mc) {
      float v0 = tanh_relu(acc[mc][0]);
      float v1 = tanh_relu(acc[mc][1]);
      float v2 = tanh_relu(acc[mc][2]);
      float v3 = tanh_relu(acc[mc][3]);
      if (diag) {
        const int nl = 16 * wr + g;
        const int ml = 32 * wc + 8 * mc + 2 * tig;
        if (ml     == nl + doff)     v0 += 0.5f;
        if (ml + 1 == nl + doff)     v1 += 0.5f;
        if (ml     == nl + 8 + doff) v2 += 0.5f;
        if (ml + 1 == nl + 8 + doff) v3 += 0.5f;
      }
      sA2[2 * mc]     = pack_h2(v0, v1);
      sA2[2 * mc + 1] = pack_h2(v2, v3);
    }

    // ---- phase 2: agg += S·H ----
    #pragma unroll
    for (int kt = 0; kt < 2; ++kt)
      #pragma unroll
      for (int nc = 0; nc < 4; ++nc)
        mma16816(acc2[nc], &sA2[4 * kt], &BH2[kt][nc >> 1][(nc & 1) * 2]);
  }

  __syncthreads();   // buf region now dead -> aggbuf

  // ---- cross-warp reduction of agg (4 m-slices) ----
  float* aggbuf = (float*)(sm + SM_AGG);
  {
    float* p = aggbuf + wc * 1024;
    const int nl = 16 * wr + g;
    #pragma unroll
    for (int nc = 0; nc < 4; ++nc) {
      const int d0 = 8 * nc + 2 * tig;
      p[nl * 32 + d0]           = acc2[nc][0];
      p[nl * 32 + d0 + 1]       = acc2[nc][1];
      p[(nl + 8) * 32 + d0]     = acc2[nc][2];
      p[(nl + 8) * 32 + d0 + 1] = acc2[nc][3];
    }
  }
  __syncthreads();

  // ---- reduce 4 slices + write partial agg to global ----
  {
    float4* a4 = (float4*)aggbuf;
    float4 s = a4[t], s1 = a4[t + 256], s2 = a4[t + 512], s3 = a4[t + 768];
    float4 r = make_float4(s.x + s1.x + s2.x + s3.x, s.y + s1.y + s2.y + s3.y,
                           s.z + s1.z + s2.z + s3.z, s.w + s1.w + s2.w + s3.w);
    float4* gout = (float4*)(g_agg + (((size_t)(mz * NB + b)) * NT + n0) * DD);
    gout[t] = r;
  }
}

// ---- epilogue: out = elu(h·Ws + (agg0+agg1)·Wn + b) [+ next-layer prep] ----
__global__ __launch_bounds__(256)
void gnn_epi(const float* __restrict__ hin_p,
             const float* __restrict__ Ws, const float* __restrict__ Wn,
             const float* __restrict__ bias, float* __restrict__ hout_p,
             int write_prep)
{
  __shared__ float sW[2080];
  __shared__ float sOut[64][33];
  const int t = threadIdx.x, b = blockIdx.y, n0 = blockIdx.x * 64;
  const float* Hin  = hin_p  ? hin_p  : (const float*)g_h1;
  float*       Hout = hout_p ? hout_p : g_h1;

  for (int i = t; i < 2 * DD * DD + DD; i += 256) {
    float v;
    if (i < 1024)      v = Ws[i];
    else if (i < 2048) v = Wn[i - 1024];
    else               v = bias[i - 2048];
    sW[i] = v;
  }
  __syncthreads();

  const int r = t >> 2, e0 = (t & 3) * 8;
  const float* hrow = Hin + ((size_t)b * NT + n0 + r) * DD;
  const float* a0 = g_agg + (((size_t)b) * NT + n0 + r) * DD;
  const float* a1 = g_agg + (((size_t)(NB + b)) * NT + n0 + r) * DD;

  float out[8];
  #pragma unroll
  for (int e = 0; e < 8; ++e) out[e] = sW[2048 + e0 + e];
  #pragma unroll
  for (int d = 0; d < DD; ++d) {
    const float hd = hrow[d];
    const float ad = a0[d] + a1[d];
    const float* ws = sW + d * DD + e0;
    const float* wn = sW + 1024 + d * DD + e0;
    #pragma unroll
    for (int e = 0; e < 8; ++e) out[e] += hd * ws[e] + ad * wn[e];
  }
  #pragma unroll
  for (int e = 0; e < 8; ++e) {
    float v = out[e];
    out[e] = v > 0.0f ? v : (__expf(v) - 1.0f);
  }
  float* orow = Hout + ((size_t)b * NT + n0 + r) * DD + e0;
  *(float4*)(orow)     = make_float4(out[0], out[1], out[2], out[3]);
  *(float4*)(orow + 4) = make_float4(out[4], out[5], out[6], out[7]);

  if (write_prep) {
    #pragma unroll
    for (int e = 0; e < 8; ++e) sOut[r][e0 + e] = out[e];
    __syncthreads();
    #pragma unroll
    for (int k = 0; k < 4; ++k) {
      const int i = t + k * 256;
      const int d = i >> 5, p = i & 31;
      g_hthi[((size_t)b * DD + d) * (NT / 2) + (n0 >> 1) + p] =
          pack_h2(sOut[2 * p][d], sOut[2 * p + 1][d]);
    }
  }
}

extern "C" void kernel_launch(void* const* d_in, const int* in_sizes, int n_in,
                              void* d_out, int out_size) {
  (void)in_sizes; (void)n_in; (void)out_size;
  const float* X  = (const float*)d_in[0];
  const float* Ws = (const float*)d_in[1];   // [2,32,32]
  const float* Wn = (const float*)d_in[2];   // [2,32,32]
  const float* bb = (const float*)d_in[3];   // [2,32]
  float* out = (float*)d_out;

  cudaFuncSetAttribute(gnn_partial,
                       cudaFuncAttributeMaxDynamicSharedMemorySize, SMEM_P);

  dim3 pgrid(NT / 64, NB), pblk(256);
  dim3 ggrid(NT / BN, NB, MSPLIT), gblk(NTHREADS);
  dim3 egrid(NT / 64, NB), eblk(256);

  prep_kernel<<<pgrid, pblk>>>(X);                         // g_xhi, g_hthi(X)
  gnn_partial<<<ggrid, gblk, SMEM_P>>>();                  // -> g_agg
  gnn_epi<<<egrid, eblk>>>(X, Ws, Wn, bb, nullptr, 1);     // -> g_h1 + g_hthi(h1)
  gnn_partial<<<ggrid, gblk, SMEM_P>>>();                  // -> g_agg
  gnn_epi<<<egrid, eblk>>>(nullptr, Ws + 1024, Wn + 1024, bb + 32, out, 0);
}

// round 9
// speedup vs baseline: 1.1665x; 1.1665x over previous
#include <cuda_runtime.h>
#include <cuda_fp16.h>
#include <cstdint>

#define NT 2560
#define DD 32
#define NB 4
#define BN 32
#define BM 128
#define MSPLIT 2
#define NITH 10                       // m-tiles per block (20 / MSPLIT)
#define NTHREADS 256

// ---- partial-kernel smem ----
#define SM_XNH 0
#define SM_BUF 2560
#define OFF_XMH 0
#define OFF_HTH 10240
#define BUFSZ   18944                 // per stage (XM + HT)
#define SMEM_P  (SM_BUF + 3 * BUFSZ)  // 59392, 3-stage ring
#define SM_AGG  SM_BUF                // 16KB reduction buffer (post-loop)
#define SM_W    (SM_AGG + 16384)      // 8320B weights (epilogue only)
#define SM_OUT  (SM_W + 8320)         // 32x33 f32 out tile (epilogue only)

// ---- device globals (allocation-free scratch) ----
__device__ float    g_h1 [NB * NT * DD];
__device__ float    g_agg[MSPLIT * NB * NT * DD];
__device__ uint32_t g_xhi [NB * NT * DD / 2];   // X fp16x2 [b][row][16]
__device__ uint32_t g_hthi[NB * DD * NT / 2];   // H^T fp16x2 [b][d][1280]
__device__ int      g_cnt[(NT / BN) * NB];      // last-block counters (self-reset)

__device__ __forceinline__ uint32_t smem_u32(const void* p) {
  uint32_t a;
  asm("{ .reg .u64 t; cvta.to.shared.u64 t, %1; cvt.u32.u64 %0, t; }" : "=r"(a) : "l"(p));
  return a;
}
__device__ __forceinline__ void mma16816(float c[4], const uint32_t a[4],
                                         const uint32_t b[2]) {
  asm volatile(
      "mma.sync.aligned.m16n8k16.row.col.f32.f16.f16.f32 "
      "{%0,%1,%2,%3}, {%4,%5,%6,%7}, {%8,%9}, {%0,%1,%2,%3};"
      : "+f"(c[0]), "+f"(c[1]), "+f"(c[2]), "+f"(c[3])
      : "r"(a[0]), "r"(a[1]), "r"(a[2]), "r"(a[3]), "r"(b[0]), "r"(b[1]));
}
__device__ __forceinline__ void ldsm4(uint32_t r[4], uint32_t addr) {
  asm volatile("ldmatrix.sync.aligned.m8n8.x4.shared.b16 {%0,%1,%2,%3}, [%4];"
               : "=r"(r[0]), "=r"(r[1]), "=r"(r[2]), "=r"(r[3]) : "r"(addr));
}
__device__ __forceinline__ void cp16(uint32_t dst, const void* src) {
  asm volatile("cp.async.cg.shared.global [%0], [%1], 16;" :: "r"(dst), "l"(src));
}
#define CP_COMMIT() asm volatile("cp.async.commit_group;")
template <int N> __device__ __forceinline__ void cp_wait() {
  asm volatile("cp.async.wait_group %0;" :: "n"(N));
}
__device__ __forceinline__ float tanh_relu(float s) {
  float r = fmaxf(s, 0.0f), v;
  asm("tanh.approx.f32 %0, %1;" : "=f"(v) : "f"(r));
  return v;
}
__device__ __forceinline__ uint32_t pack_h2(float x, float y) {
  __half2 h = __floats2half2_rn(x, y);
  return *reinterpret_cast<uint32_t*>(&h);
}

// ---- prep: fp16-convert X rows + write transposed fp16 (once) ----
__global__ void prep_kernel(const float* __restrict__ src) {
  __shared__ uint32_t sxh[64][20];
  const int t = threadIdx.x, b = blockIdx.y, r0 = blockIdx.x * 64;
  {
    const int row = t >> 2, q = t & 3;
    const float4* p = (const float4*)(src + ((size_t)b * NT + r0 + row) * DD + q * 8);
    float4 v0 = p[0], v1 = p[1];
    uint4 hv = make_uint4(pack_h2(v0.x, v0.y), pack_h2(v0.z, v0.w),
                          pack_h2(v1.x, v1.y), pack_h2(v1.z, v1.w));
    *(uint4*)&sxh[row][q * 4] = hv;
    size_t xi = ((size_t)b * NT + r0 + row) * 16 + q * 4;
    *(uint4*)&g_xhi[xi] = hv;
  }
  __syncthreads();
  {
    const int d = t >> 3;
    const uint32_t sh = (d & 1) * 16;
    const size_t obase = ((size_t)b * DD + d) * (NT / 2) + (r0 >> 1);
    #pragma unroll
    for (int j = 0; j < 4; ++j) {
      const int p = (t & 7) * 4 + j;
      uint32_t h0 = (sxh[2 * p][d >> 1] >> sh) & 0xffffu;
      uint32_t h1 = (sxh[2 * p + 1][d >> 1] >> sh) & 0xffffu;
      g_hthi[obase + p] = h0 | (h1 << 16);
    }
  }
}

// ---- fused layer: partial agg + last-block epilogue ----
__global__ __launch_bounds__(NTHREADS, 3)
void gnn_layer(const float* __restrict__ hin_p,
               const float* __restrict__ Ws, const float* __restrict__ Wn,
               const float* __restrict__ bias, float* __restrict__ hout_p,
               int write_prep)
{
  extern __shared__ char sm[];
  const uint32_t sb = smem_u32(sm);
  const int t = threadIdx.x, lane = t & 31, wid = t >> 5;
  const int wr = wid >> 2, wc = wid & 3, g = lane >> 2, tig = lane & 3;
  const int bx = blockIdx.x, b = blockIdx.y, mz = blockIdx.z;
  const int n0 = bx * BN;
  const int mtdiag = bx >> 2, doff = (bx & 3) * 32;

  // Xn tile (persistent): 32 rows x 64B fp16
  {
    const int row = t >> 3, q = t & 7;
    const size_t xi = ((size_t)b * NT + n0 + row) * 16 + q * 2;
    *(uint2*)(sm + SM_XNH + row * 80 + q * 8) = *(const uint2*)(g_xhi + xi);
  }

  // tile-issue via cp.async (4x16B per thread); 3-stage ring
  auto issue = [&](int i) {
    const int m0 = (mz * NITH + i) * BM;
    const uint32_t base = sb + SM_BUF + (uint32_t)(i % 3) * BUFSZ;
    const size_t xbase = ((size_t)b * NT + m0) * 16;
    const size_t hbase = (size_t)b * DD * (NT / 2) + (m0 >> 1);
    #pragma unroll
    for (int k = 0; k < 2; ++k) {
      const int c = t + k * 256;
      const int row = c >> 2, q = c & 3;
      cp16(base + OFF_XMH + row * 80 + q * 16, g_xhi + xbase + row * 16 + q * 4);
      const int d = c >> 4, q2 = c & 15;
      cp16(base + OFF_HTH + d * 272 + q2 * 16, g_hthi + hbase + (size_t)d * (NT / 2) + q2 * 4);
    }
    CP_COMMIT();
  };

  // ---- ldmatrix lane addresses ----
  const uint32_t a_addr = sb + SM_XNH +
      (uint32_t)(16 * wr + 8 * ((lane >> 3) & 1) + (lane & 7)) * 80u +
      (uint32_t)(lane >> 4) * 16u;
  const uint32_t b1_addr = OFF_XMH +
      (uint32_t)(32 * wc + 8 * (lane >> 4) + (lane & 7)) * 80u +
      (uint32_t)((lane >> 3) & 1) * 16u;
  const uint32_t b2_addr = OFF_HTH +
      (uint32_t)(8 * (lane >> 4) + (lane & 7)) * 272u +
      (uint32_t)(64 * wc) + (uint32_t)((lane >> 3) & 1) * 16u;

  float acc2[4][4];
  #pragma unroll
  for (int nc = 0; nc < 4; ++nc)
    #pragma unroll
    for (int e = 0; e < 4; ++e) acc2[nc][e] = 0.0f;

  issue(0);
  __syncthreads();                       // Xn stores visible

  uint32_t AH[2][4];                     // loop-invariant A (Xn)
  ldsm4(AH[0], a_addr);
  ldsm4(AH[1], a_addr + 32);

  for (int i = 0; i < NITH; ++i) {
    if (i + 1 < NITH) { issue(i + 1); cp_wait<1>(); }
    else              { cp_wait<0>(); }
    __syncthreads();

    const uint32_t buf = sb + SM_BUF + (uint32_t)(i % 3) * BUFSZ;
    const int mt = mz * NITH + i;
    const bool diag = (mt == mtdiag);

    uint32_t BH[2][2][4], BH2[2][2][4];
    #pragma unroll
    for (int kt = 0; kt < 2; ++kt)
      #pragma unroll
      for (int p = 0; p < 2; ++p) {
        ldsm4(BH[kt][p],  buf + b1_addr + p * 1280u + kt * 32u);
        ldsm4(BH2[kt][p], buf + b2_addr + p * 4352u + kt * 32u);
      }

    // ---- phase 1: S = Xn·Xm^T ----
    float acc[4][4];
    #pragma unroll
    for (int mc = 0; mc < 4; ++mc)
      #pragma unroll
      for (int e = 0; e < 4; ++e) acc[mc][e] = 0.0f;
    #pragma unroll
    for (int kt = 0; kt < 2; ++kt)
      #pragma unroll
      for (int mc = 0; mc < 4; ++mc)
        mma16816(acc[mc], AH[kt], &BH[kt][mc >> 1][(mc & 1) * 2]);

    // ---- nonlinearity + self-loop -> phase-2 A frags ----
    uint32_t sA2[8];
    #pragma unroll
    for (int mc = 0; mc < 4; ++mc) {
      float v0 = tanh_relu(acc[mc][0]);
      float v1 = tanh_relu(acc[mc][1]);
      float v2 = tanh_relu(acc[mc][2]);
      float v3 = tanh_relu(acc[mc][3]);
      if (diag) {
        const int nl = 16 * wr + g;
        const int ml = 32 * wc + 8 * mc + 2 * tig;
        if (ml     == nl + doff)     v0 += 0.5f;
        if (ml + 1 == nl + doff)     v1 += 0.5f;
        if (ml     == nl + 8 + doff) v2 += 0.5f;
        if (ml + 1 == nl + 8 + doff) v3 += 0.5f;
      }
      sA2[2 * mc]     = pack_h2(v0, v1);
      sA2[2 * mc + 1] = pack_h2(v2, v3);
    }

    // ---- phase 2: agg += S·H ----
    #pragma unroll
    for (int kt = 0; kt < 2; ++kt)
      #pragma unroll
      for (int nc = 0; nc < 4; ++nc)
        mma16816(acc2[nc], &sA2[4 * kt], &BH2[kt][nc >> 1][(nc & 1) * 2]);
  }

  __syncthreads();   // buf region dead -> reduction buffer

  // ---- cross-warp reduction of agg (4 m-slices) ----
  float* aggbuf = (float*)(sm + SM_AGG);
  {
    float* p = aggbuf + wc * 1024;
    const int nl = 16 * wr + g;
    #pragma unroll
    for (int nc = 0; nc < 4; ++nc) {
      const int d0 = 8 * nc + 2 * tig;
      p[nl * 32 + d0]           = acc2[nc][0];
      p[nl * 32 + d0 + 1]       = acc2[nc][1];
      p[(nl + 8) * 32 + d0]     = acc2[nc][2];
      p[(nl + 8) * 32 + d0 + 1] = acc2[nc][3];
    }
  }
  __syncthreads();

  // ---- reduce 4 slices + write partial agg to this block's slot ----
  {
    float4* a4 = (float4*)aggbuf;
    float4 s = a4[t], s1 = a4[t + 256], s2 = a4[t + 512], s3 = a4[t + 768];
    float4 r = make_float4(s.x + s1.x + s2.x + s3.x, s.y + s1.y + s2.y + s3.y,
                           s.z + s1.z + s2.z + s3.z, s.w + s1.w + s2.w + s3.w);
    float4* gout = (float4*)(g_agg + (((size_t)(mz * NB + b)) * NT + n0) * DD);
    gout[t] = r;
  }

  // ---- last-block detection ----
  __shared__ int s_last;
  __threadfence();
  __syncthreads();
  if (t == 0) {
    int old = atomicAdd(&g_cnt[bx * NB + b], 1);
    s_last = (old == MSPLIT - 1);
    if (old == MSPLIT - 1) g_cnt[bx * NB + b] = 0;   // self-reset for next launch
  }
  __syncthreads();
  if (!s_last) return;
  __threadfence();

  // ---- epilogue (last block only): out = elu(h·Ws + (agg0+agg1)·Wn + b) ----
  const float* Hin  = hin_p  ? hin_p  : (const float*)g_h1;
  float*       Hout = hout_p ? hout_p : g_h1;

  float* sW = (float*)(sm + SM_W);
  for (int i = t; i < 2 * DD * DD + DD; i += NTHREADS) {
    float v;
    if (i < 1024)      v = Ws[i];
    else if (i < 2048) v = Wn[i - 1024];
    else               v = bias[i - 2048];
    sW[i] = v;
  }
  __syncthreads();

  const int r = t >> 3, e0 = (t & 7) * 4;
  float h[DD], a[DD];
  {
    const float4* hr = (const float4*)(Hin + ((size_t)b * NT + n0 + r) * DD);
    const float4* p0 = (const float4*)(g_agg + (((size_t)b) * NT + n0 + r) * DD);
    const float4* p1 = (const float4*)(g_agg + (((size_t)(NB + b)) * NT + n0 + r) * DD);
    #pragma unroll
    for (int q = 0; q < 8; ++q) {
      float4 v = hr[q];
      h[4 * q] = v.x; h[4 * q + 1] = v.y; h[4 * q + 2] = v.z; h[4 * q + 3] = v.w;
      float4 x0 = __ldcg(p0 + q);        // L2-coherent: peer block's writes
      float4 x1 = __ldcg(p1 + q);
      a[4 * q]     = x0.x + x1.x; a[4 * q + 1] = x0.y + x1.y;
      a[4 * q + 2] = x0.z + x1.z; a[4 * q + 3] = x0.w + x1.w;
    }
  }
  float out[4];
  #pragma unroll
  for (int e = 0; e < 4; ++e) out[e] = sW[2048 + e0 + e];
  #pragma unroll
  for (int d = 0; d < DD; ++d) {
    const float hd = h[d];
    const float ad = a[d];
    const float* ws = sW + d * DD + e0;
    const float* wn = sW + 1024 + d * DD + e0;
    #pragma unroll
    for (int e = 0; e < 4; ++e) out[e] += hd * ws[e] + ad * wn[e];
  }
  #pragma unroll
  for (int e = 0; e < 4; ++e) {
    float v = out[e];
    out[e] = v > 0.0f ? v : (__expf(v) - 1.0f);
  }
  *(float4*)(Hout + ((size_t)b * NT + n0 + r) * DD + e0) =
      make_float4(out[0], out[1], out[2], out[3]);

  // ---- fused next-layer prep: transposed fp16 H write ----
  if (write_prep) {
    float* sOut = (float*)(sm + SM_OUT);           // [32][33]
    #pragma unroll
    for (int e = 0; e < 4; ++e) sOut[r * 33 + e0 + e] = out[e];
    __syncthreads();
    #pragma unroll
    for (int k = 0; k < 2; ++k) {
      const int i = t + k * 256;                   // 512 = 32d x 16p
      const int d = i >> 4, p = i & 15;
      g_hthi[((size_t)b * DD + d) * (NT / 2) + (n0 >> 1) + p] =
          pack_h2(sOut[(2 * p) * 33 + d], sOut[(2 * p + 1) * 33 + d]);
    }
  }
}

extern "C" void kernel_launch(void* const* d_in, const int* in_sizes, int n_in,
                              void* d_out, int out_size) {
  (void)in_sizes; (void)n_in; (void)out_size;
  const float* X  = (const float*)d_in[0];
  const float* Ws = (const float*)d_in[1];   // [2,32,32]
  const float* Wn = (const float*)d_in[2];   // [2,32,32]
  const float* bb = (const float*)d_in[3];   // [2,32]
  float* out = (float*)d_out;

  cudaFuncSetAttribute(gnn_layer,
                       cudaFuncAttributeMaxDynamicSharedMemorySize, SMEM_P);

  dim3 pgrid(NT / 64, NB), pblk(256);
  dim3 ggrid(NT / BN, NB, MSPLIT), gblk(NTHREADS);

  prep_kernel<<<pgrid, pblk>>>(X);                               // g_xhi, g_hthi(X)
  gnn_layer<<<ggrid, gblk, SMEM_P>>>(X, Ws, Wn, bb, nullptr, 1); // -> g_h1 + g_hthi(h1)
  gnn_layer<<<ggrid, gblk, SMEM_P>>>(nullptr, Ws + 1024, Wn + 1024, bb + 32, out, 0);
}